// round 12
// baseline (speedup 1.0000x reference)
#include <cuda_runtime.h>
#include <cuda_bf16.h>
#include <math.h>
#include <stdint.h>

#define B_   32
#define S_   1024
#define DM   48
#define NH   3
#define DK   16
#define BH_  (B_*NH)            // 96
#define H_ELEMS (B_*S_*DM)      // 1572864

typedef unsigned long long ull;

// Scratch (no allocations allowed)
__device__ float g_Q[BH_*S_*DK];
__device__ float g_K[BH_*S_*DK];
__device__ float g_V[BH_*S_*DK];
__device__ float g_Hcat[B_*S_*DM];

// ---------------------------------------------------------------------------
// Linear kernels
// ---------------------------------------------------------------------------
__device__ __forceinline__ void lin_core(const float* __restrict__ X,
    const float* __restrict__ W, const float* __restrict__ bias,
    int row0, float scale, float* __restrict__ out, int headsplit)
{
    __shared__ float Ws[48*49];
    __shared__ float bs[48];
    __shared__ __align__(16) float Xs[128*48];
    int tid = threadIdx.x;
    for (int i = tid; i < 48*48; i += 384) Ws[(i/48)*49 + (i%48)] = W[i];
    if (tid < 48) bs[tid] = bias[tid];
    const float4* Xg4 = (const float4*)(X + row0*48);
    float4* Xs4 = (float4*)Xs;
    for (int i = tid; i < 1536; i += 384) Xs4[i] = Xg4[i];
    __syncthreads();

    int r0 = tid / 12, jg = tid % 12;
    float acc[4][4];
#pragma unroll
    for (int rr = 0; rr < 4; rr++)
#pragma unroll
        for (int jj = 0; jj < 4; jj++) acc[rr][jj] = bs[jg*4 + jj];

#pragma unroll
    for (int c4 = 0; c4 < 12; c4++) {
        float4 xv4[4];
#pragma unroll
        for (int rr = 0; rr < 4; rr++)
            xv4[rr] = *(const float4*)&Xs[(r0 + 32*rr)*48 + c4*4];
#pragma unroll
        for (int jj = 0; jj < 4; jj++) {
            const float* wr = &Ws[(jg*4 + jj)*49 + c4*4];
            float w0 = wr[0], w1 = wr[1], w2 = wr[2], w3 = wr[3];
#pragma unroll
            for (int rr = 0; rr < 4; rr++) {
                acc[rr][jj] = fmaf(xv4[rr].x, w0, acc[rr][jj]);
                acc[rr][jj] = fmaf(xv4[rr].y, w1, acc[rr][jj]);
                acc[rr][jj] = fmaf(xv4[rr].z, w2, acc[rr][jj]);
                acc[rr][jj] = fmaf(xv4[rr].w, w3, acc[rr][jj]);
            }
        }
    }

    int j0 = jg * 4;
#pragma unroll
    for (int rr = 0; rr < 4; rr++) {
        int grow = row0 + r0 + 32*rr;
        float4 v = make_float4(acc[rr][0]*scale, acc[rr][1]*scale,
                               acc[rr][2]*scale, acc[rr][3]*scale);
        if (headsplit) {
            int b = grow >> 10, s = grow & 1023;
            int h = j0 >> 4,  d = j0 & 15;
            *(float4*)(out + ((b*NH + h)*S_ + s)*DK + d) = v;
        } else {
            *(float4*)(out + grow*48 + j0) = v;
        }
    }
}

__global__ __launch_bounds__(384) void qkv48(
    const float* __restrict__ Xq, const float* __restrict__ Wq, const float* __restrict__ bq,
    const float* __restrict__ Xk, const float* __restrict__ Wk, const float* __restrict__ bk,
    const float* __restrict__ Xv, const float* __restrict__ Wv, const float* __restrict__ bv)
{
    int m = blockIdx.y;
    const float *X, *W, *bb; float* dst; float scale;
    // Q scale folds 1/sqrt(dk) AND log2(e): attention uses ex2 directly.
    if (m == 0)      { X = Xq; W = Wq; bb = bq; dst = g_Q; scale = 0.25f * 1.4426950408889634f; }
    else if (m == 1) { X = Xk; W = Wk; bb = bk; dst = g_K; scale = 1.0f; }
    else             { X = Xv; W = Wv; bb = bv; dst = g_V; scale = 1.0f; }
    lin_core(X, W, bb, blockIdx.x * 128, scale, dst, 1);
}

__global__ __launch_bounds__(384) void proj48(
    const float* __restrict__ Wh, const float* __restrict__ bhp, float* __restrict__ out)
{
    lin_core((const float*)g_Hcat, Wh, bhp, blockIdx.x * 128, 1.0f, out, 0);
}

// ---------------------------------------------------------------------------
// split fp32 pair -> (bf16x2 hi, bf16x2 lo). Low 16 bits = first value.
// ---------------------------------------------------------------------------
__device__ __forceinline__ void split2(float e0, float e1, uint32_t& h2, uint32_t& l2) {
    uint32_t h;
    asm("cvt.rn.bf16x2.f32 %0, %1, %2;" : "=r"(h) : "f"(e1), "f"(e0));
    float h0 = __uint_as_float(h << 16);
    float h1 = __uint_as_float(h & 0xFFFF0000u);
    uint32_t l;
    asm("cvt.rn.bf16x2.f32 %0, %1, %2;" : "=r"(l) : "f"(e1 - h1), "f"(e0 - h0));
    h2 = h; l2 = l;
}

// mma.sync m16n8k16 row.col f32.bf16.bf16.f32, D accumulates in place.
__device__ __forceinline__ void mma_bf16(float d[4], const uint32_t a[4], const uint32_t b[2]) {
    asm volatile(
        "mma.sync.aligned.m16n8k16.row.col.f32.bf16.bf16.f32 "
        "{%0,%1,%2,%3}, {%4,%5,%6,%7}, {%8,%9}, {%0,%1,%2,%3};"
        : "+f"(d[0]), "+f"(d[1]), "+f"(d[2]), "+f"(d[3])
        : "r"(a[0]), "r"(a[1]), "r"(a[2]), "r"(a[3]), "r"(b[0]), "r"(b[1]));
}

// smem layout (u32 units): khi[8192] klo[8192] vhi[8192] vlo[8192]
// then A-stage: 16 warps x 16 rows x 66 floats = 16896 floats (aliases the
// K/V build staging, which only needs 4096 floats and is used earlier).
#define SMO_KHI   0
#define SMO_KLO   8192
#define SMO_VHI   16384
#define SMO_VLO   24576
#define SMO_STAGE 32768
#define STAGE_F   (16*16*66)              // 16896
#define SMEM_BYTES ((32768 + STAGE_F) * 4)  // 198656

// ---------------------------------------------------------------------------
// Tensor-core attention via mma.sync (plain sm_103 target — no tcgen05).
// CTA = (qtile of 256 rows, bh). 512 thr = 16 warps; warp owns 16 q rows.
// K/V pre-split to bf16 hi/lo fragments in smem (shared by all warps).
// Pass 1: scores = 3x split MMA -> ex2 -> row sums (quad reduce) -> inv.
// Pass 2: recompute scores, normalize, stage e in per-warp smem tile
//         (col-rotated by 8*row to spread STS banks), drain every 64 cols
//         as contiguous 256B-per-row STG.128. Drain LDS uses float2 pairs
//         (stride 66 is NOT 16B-aligned for odd rows — LDS.128 would trap).
//         AV = 3x split MMA per d-tile from registers. Hcat direct.
// ---------------------------------------------------------------------------
__global__ __launch_bounds__(512, 1) void attn_mma(float* __restrict__ Aout)
{
    extern __shared__ __align__(16) uint32_t smu[];
    uint32_t* khi = smu + SMO_KHI;
    uint32_t* klo = smu + SMO_KLO;
    uint32_t* vhi = smu + SMO_VHI;
    uint32_t* vlo = smu + SMO_VLO;
    float* stage  = (float*)(smu + SMO_STAGE);

    int qt = blockIdx.x, bh = blockIdx.y;
    int tid = threadIdx.x, warp = tid >> 5, lane = tid & 31;
    int tg = lane & 3, gid = lane >> 2;
    int q0 = qt * 256;

    // ---- build K fragments (4 rounds of 256 seq rows) ----
    const float4* Kg4 = (const float4*)(g_K + bh*(S_*DK));
    for (int r = 0; r < 4; r++) {
        for (int i = tid; i < 1024; i += 512)
            ((float4*)stage)[i] = Kg4[r*1024 + i];
        __syncthreads();
        for (int e = tid; e < 2048; e += 512) {
            int tl = e >> 6, rem = e & 63, reg = rem >> 5, ln = rem & 31;
            int krow = tl*8 + (ln >> 2), dk = reg*8 + (ln & 3)*2;
            float2 v = *(const float2*)(stage + krow*16 + dk);
            uint32_t h, l; split2(v.x, v.y, h, l);
            int t = r*32 + tl;
            khi[(t*32 + ln)*2 + reg] = h;
            klo[(t*32 + ln)*2 + reg] = l;
        }
        __syncthreads();
    }
    // ---- build V fragments (4 rounds) ----
    const float4* Vg4 = (const float4*)(g_V + bh*(S_*DK));
    for (int r = 0; r < 4; r++) {
        for (int i = tid; i < 1024; i += 512)
            ((float4*)stage)[i] = Vg4[r*1024 + i];
        __syncthreads();
        for (int e = tid; e < 2048; e += 512) {
            int kcl = e >> 7, rem = e & 127, t = rem >> 6, reg = (rem >> 5) & 1, ln = rem & 31;
            int klc = kcl*16 + reg*8 + (ln & 3)*2, d = t*8 + (ln >> 2);
            float v0 = stage[klc*16 + d];
            float v1 = stage[(klc + 1)*16 + d];
            uint32_t h, l; split2(v0, v1, h, l);
            int kc = r*16 + kcl;
            vhi[((kc*2 + t)*32 + ln)*2 + reg] = h;
            vlo[((kc*2 + t)*32 + ln)*2 + reg] = l;
        }
        __syncthreads();
    }

    // ---- Q A-fragment (m16 x k16 = one MMA step), split hi/lo ----
    uint32_t qhi[4], qlo[4];
    {
        const float* Qp = g_Q + (bh*S_ + q0 + warp*16)*DK;
        float2 x;
        x = *(const float2*)(Qp + gid*16 + tg*2);           split2(x.x, x.y, qhi[0], qlo[0]);
        x = *(const float2*)(Qp + (gid+8)*16 + tg*2);       split2(x.x, x.y, qhi[1], qlo[1]);
        x = *(const float2*)(Qp + gid*16 + tg*2 + 8);       split2(x.x, x.y, qhi[2], qlo[2]);
        x = *(const float2*)(Qp + (gid+8)*16 + tg*2 + 8);   split2(x.x, x.y, qhi[3], qlo[3]);
    }

    // ---- pass 1: row sums ----
    float ls0 = 0.f, ls1 = 0.f;
#pragma unroll 2
    for (int t = 0; t < 128; t++) {
        uint32_t kb[2], kl2[2];
        *(uint2*)kb  = *(const uint2*)(khi + (t*32 + lane)*2);
        *(uint2*)kl2 = *(const uint2*)(klo + (t*32 + lane)*2);
        float d[4] = {0.f, 0.f, 0.f, 0.f};
        mma_bf16(d, qhi, kb);
        mma_bf16(d, qhi, kl2);
        mma_bf16(d, qlo, kb);
        float e0, e1, e2, e3;
        asm("ex2.approx.f32 %0,%1;" : "=f"(e0) : "f"(d[0]));
        asm("ex2.approx.f32 %0,%1;" : "=f"(e1) : "f"(d[1]));
        asm("ex2.approx.f32 %0,%1;" : "=f"(e2) : "f"(d[2]));
        asm("ex2.approx.f32 %0,%1;" : "=f"(e3) : "f"(d[3]));
        ls0 += e0 + e1;
        ls1 += e2 + e3;
    }
    ls0 += __shfl_xor_sync(0xffffffffu, ls0, 1);
    ls0 += __shfl_xor_sync(0xffffffffu, ls0, 2);
    ls1 += __shfl_xor_sync(0xffffffffu, ls1, 1);
    ls1 += __shfl_xor_sync(0xffffffffu, ls1, 2);
    float inv0 = 1.0f / ls0, inv1 = 1.0f / ls1;

    // ---- pass 2: staged A stores + AV ----
    float cA[4] = {0.f, 0.f, 0.f, 0.f};   // d cols 0..7
    float cB[4] = {0.f, 0.f, 0.f, 0.f};   // d cols 8..15
    float* Ab = Aout + ((size_t)(bh*S_ + q0 + warp*16))*S_;
    float* wst = stage + warp*(16*66);    // per-warp stage: 16 rows x 66

    // STS column rotation: physical = (logical + 8*(row&7)) & 63
    int rotA = 8 * (gid & 7);             // rows gid and gid+8 share gid&7

#pragma unroll 1
    for (int kc = 0; kc < 64; kc++) {
        float e[2][4];
#pragma unroll
        for (int s = 0; s < 2; s++) {
            int t = kc*2 + s;
            uint32_t kb[2], kl2[2];
            *(uint2*)kb  = *(const uint2*)(khi + (t*32 + lane)*2);
            *(uint2*)kl2 = *(const uint2*)(klo + (t*32 + lane)*2);
            float d[4] = {0.f, 0.f, 0.f, 0.f};
            mma_bf16(d, qhi, kb);
            mma_bf16(d, qhi, kl2);
            mma_bf16(d, qlo, kb);
            float t0, t1, t2, t3;
            asm("ex2.approx.f32 %0,%1;" : "=f"(t0) : "f"(d[0]));
            asm("ex2.approx.f32 %0,%1;" : "=f"(t1) : "f"(d[1]));
            asm("ex2.approx.f32 %0,%1;" : "=f"(t2) : "f"(d[2]));
            asm("ex2.approx.f32 %0,%1;" : "=f"(t3) : "f"(d[3]));
            e[s][0] = t0 * inv0; e[s][1] = t1 * inv0;
            e[s][2] = t2 * inv1; e[s][3] = t3 * inv1;
            // stage (logical col within 64-col group = (t&7)*8 + tg*2)
            int lc = (t & 7)*8 + tg*2;
            int pc = (lc + rotA) & 63;
            *(float2*)(wst + gid*66 + pc)     = make_float2(e[s][0], e[s][1]);
            *(float2*)(wst + (gid+8)*66 + pc) = make_float2(e[s][2], e[s][3]);
        }
        // repack normalized e -> A-fragment (m16 x k16), split hi/lo
        uint32_t ahi[4], alo[4];
        split2(e[0][0], e[0][1], ahi[0], alo[0]);
        split2(e[0][2], e[0][3], ahi[1], alo[1]);
        split2(e[1][0], e[1][1], ahi[2], alo[2]);
        split2(e[1][2], e[1][3], ahi[3], alo[3]);
        // AV: two d-tiles (cols 0..7, 8..15)
        {
            uint32_t vb[2], vl2[2];
            *(uint2*)vb  = *(const uint2*)(vhi + ((kc*2 + 0)*32 + lane)*2);
            *(uint2*)vl2 = *(const uint2*)(vlo + ((kc*2 + 0)*32 + lane)*2);
            mma_bf16(cA, ahi, vb);
            mma_bf16(cA, ahi, vl2);
            mma_bf16(cA, alo, vb);
        }
        {
            uint32_t vb[2], vl2[2];
            *(uint2*)vb  = *(const uint2*)(vhi + ((kc*2 + 1)*32 + lane)*2);
            *(uint2*)vl2 = *(const uint2*)(vlo + ((kc*2 + 1)*32 + lane)*2);
            mma_bf16(cB, ahi, vb);
            mma_bf16(cB, ahi, vl2);
            mma_bf16(cB, alo, vb);
        }
        // drain every 4 kc (= 64 cols): LDS.64 pairs (stride 66 is not 16B-
        // aligned for odd rows), recombine, coalesced STG.128 to A.
        if ((kc & 3) == 3) {
            __syncwarp();
            int grp = kc >> 2;
#pragma unroll
            for (int i = 0; i < 8; i++) {
                int row = i*2 + (lane >> 4);
                int lc  = (lane & 15) * 4;
                int pc  = (lc + 8*(row & 7)) & 63;
                float2 v0 = *(float2*)(wst + row*66 + pc);
                float2 v1 = *(float2*)(wst + row*66 + pc + 2);
                *(float4*)(Ab + (size_t)row*S_ + grp*64 + lc) =
                    make_float4(v0.x, v0.y, v1.x, v1.y);
            }
            __syncwarp();
        }
    }

    // ---- epilogue: Hcat (already normalized) ----
    {
        int b = bh / NH, h = bh - (bh / NH)*NH;
        float* Hp = g_Hcat + ((size_t)(b*S_ + q0 + warp*16))*DM + h*DK;
        *(float2*)(Hp + gid*DM + tg*2)           = make_float2(cA[0], cA[1]);
        *(float2*)(Hp + (gid+8)*DM + tg*2)       = make_float2(cA[2], cA[3]);
        *(float2*)(Hp + gid*DM + 8 + tg*2)       = make_float2(cB[0], cB[1]);
        *(float2*)(Hp + (gid+8)*DM + 8 + tg*2)   = make_float2(cB[2], cB[3]);
    }
}

// ---------------------------------------------------------------------------
extern "C" void kernel_launch(void* const* d_in, const int* in_sizes, int n_in,
                              void* d_out, int out_size)
{
    const float* Xq = (const float*)d_in[0];
    const float* Xk = (const float*)d_in[1];
    const float* Xv = (const float*)d_in[2];
    const float* Wq = (const float*)d_in[3];
    const float* bq = (const float*)d_in[4];
    const float* bk_ = (const float*)d_in[6];
    const float* Wk = (const float*)d_in[5];
    const float* Wv = (const float*)d_in[7];
    const float* bv = (const float*)d_in[8];
    const float* Wh = (const float*)d_in[9];
    const float* bh = (const float*)d_in[10];

    float* outH = (float*)d_out;
    float* outA = (float*)d_out + H_ELEMS;

    cudaFuncSetAttribute(attn_mma, cudaFuncAttributeMaxDynamicSharedMemorySize, SMEM_BYTES);

    qkv48<<<dim3(256, 3), 384>>>(Xq, Wq, bq, Xk, Wk, bk_, Xv, Wv, bv);
    attn_mma<<<dim3(4, BH_), 512, SMEM_BYTES>>>(outA);
    proj48<<<256, 384>>>(Wh, bh, outH);
}

// round 13
// speedup vs baseline: 1.0027x; 1.0027x over previous
#include <cuda_runtime.h>
#include <cuda_bf16.h>
#include <math.h>
#include <stdint.h>

#define B_   32
#define S_   1024
#define DM   48
#define NH   3
#define DK   16
#define BH_  (B_*NH)            // 96
#define H_ELEMS (B_*S_*DM)      // 1572864

typedef unsigned long long ull;

// Scratch (no allocations allowed)
__device__ float g_Q[BH_*S_*DK];
__device__ float g_K[BH_*S_*DK];
__device__ float g_V[BH_*S_*DK];
__device__ float g_Hcat[B_*S_*DM];

// ---------------------------------------------------------------------------
// Linear kernels — R4 lin_core (best measured variant, 27.6us for qkv)
// ---------------------------------------------------------------------------
__device__ __forceinline__ void lin_core(const float* __restrict__ X,
    const float* __restrict__ W, const float* __restrict__ bias,
    int row0, float scale, float* __restrict__ out, int headsplit)
{
    __shared__ float Ws[48*49];
    __shared__ float bs[48];
    __shared__ __align__(16) float Xs[128*48];
    int tid = threadIdx.x;
    for (int i = tid; i < 48*48; i += 384) Ws[(i/48)*49 + (i%48)] = W[i];
    if (tid < 48) bs[tid] = bias[tid];
    const float4* Xg4 = (const float4*)(X + row0*48);
    float4* Xs4 = (float4*)Xs;
    for (int i = tid; i < 1536; i += 384) Xs4[i] = Xg4[i];
    __syncthreads();

    int r0 = tid / 12, jg = tid % 12;
    float acc[4][4];
#pragma unroll
    for (int rr = 0; rr < 4; rr++)
#pragma unroll
        for (int jj = 0; jj < 4; jj++) acc[rr][jj] = bs[jg*4 + jj];

#pragma unroll 4
    for (int c = 0; c < 48; c++) {
        float xv[4], wv[4];
#pragma unroll
        for (int rr = 0; rr < 4; rr++) xv[rr] = Xs[(r0 + 32*rr)*48 + c];
#pragma unroll
        for (int jj = 0; jj < 4; jj++) wv[jj] = Ws[(jg*4 + jj)*49 + c];
#pragma unroll
        for (int rr = 0; rr < 4; rr++)
#pragma unroll
            for (int jj = 0; jj < 4; jj++)
                acc[rr][jj] = fmaf(xv[rr], wv[jj], acc[rr][jj]);
    }

    int j0 = jg * 4;
#pragma unroll
    for (int rr = 0; rr < 4; rr++) {
        int grow = row0 + r0 + 32*rr;
        float4 v = make_float4(acc[rr][0]*scale, acc[rr][1]*scale,
                               acc[rr][2]*scale, acc[rr][3]*scale);
        if (headsplit) {
            int b = grow >> 10, s = grow & 1023;
            int h = j0 >> 4,  d = j0 & 15;
            *(float4*)(out + ((b*NH + h)*S_ + s)*DK + d) = v;
        } else {
            *(float4*)(out + grow*48 + j0) = v;
        }
    }
}

__global__ __launch_bounds__(384) void qkv48(
    const float* __restrict__ Xq, const float* __restrict__ Wq, const float* __restrict__ bq,
    const float* __restrict__ Xk, const float* __restrict__ Wk, const float* __restrict__ bk,
    const float* __restrict__ Xv, const float* __restrict__ Wv, const float* __restrict__ bv)
{
    int m = blockIdx.y;
    const float *X, *W, *bb; float* dst; float scale;
    // Q scale folds 1/sqrt(dk) AND log2(e): attention uses ex2 directly.
    if (m == 0)      { X = Xq; W = Wq; bb = bq; dst = g_Q; scale = 0.25f * 1.4426950408889634f; }
    else if (m == 1) { X = Xk; W = Wk; bb = bk; dst = g_K; scale = 1.0f; }
    else             { X = Xv; W = Wv; bb = bv; dst = g_V; scale = 1.0f; }
    lin_core(X, W, bb, blockIdx.x * 128, scale, dst, 1);
}

__global__ __launch_bounds__(384) void proj48(
    const float* __restrict__ Wh, const float* __restrict__ bhp, float* __restrict__ out)
{
    lin_core((const float*)g_Hcat, Wh, bhp, blockIdx.x * 128, 1.0f, out, 0);
}

// ---------------------------------------------------------------------------
// split fp32 pair -> (bf16x2 hi, bf16x2 lo). Low 16 bits = first value.
// ---------------------------------------------------------------------------
__device__ __forceinline__ void split2(float e0, float e1, uint32_t& h2, uint32_t& l2) {
    uint32_t h;
    asm("cvt.rn.bf16x2.f32 %0, %1, %2;" : "=r"(h) : "f"(e1), "f"(e0));
    float h0 = __uint_as_float(h << 16);
    float h1 = __uint_as_float(h & 0xFFFF0000u);
    uint32_t l;
    asm("cvt.rn.bf16x2.f32 %0, %1, %2;" : "=r"(l) : "f"(e1 - h1), "f"(e0 - h0));
    h2 = h; l2 = l;
}

// mma.sync m16n8k16 row.col f32.bf16.bf16.f32, D accumulates in place.
__device__ __forceinline__ void mma_bf16(float d[4], const uint32_t a[4], const uint32_t b[2]) {
    asm volatile(
        "mma.sync.aligned.m16n8k16.row.col.f32.bf16.bf16.f32 "
        "{%0,%1,%2,%3}, {%4,%5,%6,%7}, {%8,%9}, {%0,%1,%2,%3};"
        : "+f"(d[0]), "+f"(d[1]), "+f"(d[2]), "+f"(d[3])
        : "r"(a[0]), "r"(a[1]), "r"(a[2]), "r"(a[3]), "r"(b[0]), "r"(b[1]));
}

// smem layout (u32 units): khi[8192] klo[8192] vhi[8192] vlo[8192] stage[4096]
#define SMO_KHI   0
#define SMO_KLO   8192
#define SMO_VHI   16384
#define SMO_VLO   24576
#define SMO_STAGE 32768
#define SMEM_BYTES ((32768 + 4096) * 4)   // 147456

// ---------------------------------------------------------------------------
// Tensor-core attention via mma.sync — SINGLE PASS, deferred normalization.
// CTA = (qtile of 256 rows, bh). 512 thr = 16 warps; warp owns 16 q rows.
// K/V pre-split to bf16 hi/lo fragments in smem (shared by all warps).
// Main loop (per 16-k chunk): scores = 3x split MMA -> ex2 -> UNNORMALIZED
//   e stored to A (quad-sector-coalesced STG.64, proven R10 pattern), lsum
//   accumulated, e repacked lane-locally into A-fragments, AV = 3x split
//   MMA per d-tile into fp32 accums (two sets, kc-parity, to split RAW
//   chains). Epilogue: row sums -> inv; Hcat = (sum of accums)*inv; then
//   each lane rescales exactly the A elements IT wrote (same-thread
//   same-address -> no fence; L2-resident re-read).
// ---------------------------------------------------------------------------
__global__ __launch_bounds__(512, 1) void attn_mma(float* __restrict__ Aout)
{
    extern __shared__ __align__(16) uint32_t smu[];
    uint32_t* khi = smu + SMO_KHI;
    uint32_t* klo = smu + SMO_KLO;
    uint32_t* vhi = smu + SMO_VHI;
    uint32_t* vlo = smu + SMO_VLO;
    float* stage  = (float*)(smu + SMO_STAGE);

    int qt = blockIdx.x, bh = blockIdx.y;
    int tid = threadIdx.x, warp = tid >> 5, lane = tid & 31;
    int tg = lane & 3, gid = lane >> 2;
    int q0 = qt * 256;

    // ---- build K fragments (4 rounds of 256 seq rows) ----
    const float4* Kg4 = (const float4*)(g_K + bh*(S_*DK));
    for (int r = 0; r < 4; r++) {
        for (int i = tid; i < 1024; i += 512)
            ((float4*)stage)[i] = Kg4[r*1024 + i];
        __syncthreads();
        for (int e = tid; e < 2048; e += 512) {
            int tl = e >> 6, rem = e & 63, reg = rem >> 5, ln = rem & 31;
            int krow = tl*8 + (ln >> 2), dk = reg*8 + (ln & 3)*2;
            float2 v = *(const float2*)(stage + krow*16 + dk);
            uint32_t h, l; split2(v.x, v.y, h, l);
            int t = r*32 + tl;
            khi[(t*32 + ln)*2 + reg] = h;
            klo[(t*32 + ln)*2 + reg] = l;
        }
        __syncthreads();
    }
    // ---- build V fragments (4 rounds) ----
    const float4* Vg4 = (const float4*)(g_V + bh*(S_*DK));
    for (int r = 0; r < 4; r++) {
        for (int i = tid; i < 1024; i += 512)
            ((float4*)stage)[i] = Vg4[r*1024 + i];
        __syncthreads();
        for (int e = tid; e < 2048; e += 512) {
            int kcl = e >> 7, rem = e & 127, t = rem >> 6, reg = (rem >> 5) & 1, ln = rem & 31;
            int klc = kcl*16 + reg*8 + (ln & 3)*2, d = t*8 + (ln >> 2);
            float v0 = stage[klc*16 + d];
            float v1 = stage[(klc + 1)*16 + d];
            uint32_t h, l; split2(v0, v1, h, l);
            int kc = r*16 + kcl;
            vhi[((kc*2 + t)*32 + ln)*2 + reg] = h;
            vlo[((kc*2 + t)*32 + ln)*2 + reg] = l;
        }
        __syncthreads();
    }

    // ---- Q A-fragment (m16 x k16 = one MMA step), split hi/lo ----
    uint32_t qhi[4], qlo[4];
    {
        const float* Qp = g_Q + (bh*S_ + q0 + warp*16)*DK;
        float2 x;
        x = *(const float2*)(Qp + gid*16 + tg*2);           split2(x.x, x.y, qhi[0], qlo[0]);
        x = *(const float2*)(Qp + (gid+8)*16 + tg*2);       split2(x.x, x.y, qhi[1], qlo[1]);
        x = *(const float2*)(Qp + gid*16 + tg*2 + 8);       split2(x.x, x.y, qhi[2], qlo[2]);
        x = *(const float2*)(Qp + (gid+8)*16 + tg*2 + 8);   split2(x.x, x.y, qhi[3], qlo[3]);
    }

    // ---- single main pass: unnormalized A stores + lsum + AV ----
    float ls0 = 0.f, ls1 = 0.f;
    float cA[4] = {0.f, 0.f, 0.f, 0.f};   // d cols 0..7,  even kc
    float cB[4] = {0.f, 0.f, 0.f, 0.f};   // d cols 8..15, even kc
    float cC[4] = {0.f, 0.f, 0.f, 0.f};   // d cols 0..7,  odd kc
    float cD[4] = {0.f, 0.f, 0.f, 0.f};   // d cols 8..15, odd kc
    float* Ab = Aout + ((size_t)(bh*S_ + q0 + warp*16))*S_;
    float* Ar1 = Ab + (size_t)gid*S_ + tg*2;
    float* Ar2 = Ab + (size_t)(gid+8)*S_ + tg*2;

#pragma unroll 1
    for (int kc = 0; kc < 64; kc++) {
        float e[2][4];
#pragma unroll
        for (int s = 0; s < 2; s++) {
            int t = kc*2 + s;
            uint32_t kb[2], kl2[2];
            *(uint2*)kb  = *(const uint2*)(khi + (t*32 + lane)*2);
            *(uint2*)kl2 = *(const uint2*)(klo + (t*32 + lane)*2);
            float d[4] = {0.f, 0.f, 0.f, 0.f};
            mma_bf16(d, qhi, kb);
            mma_bf16(d, qhi, kl2);
            mma_bf16(d, qlo, kb);
            float t0, t1, t2, t3;
            asm("ex2.approx.f32 %0,%1;" : "=f"(t0) : "f"(d[0]));
            asm("ex2.approx.f32 %0,%1;" : "=f"(t1) : "f"(d[1]));
            asm("ex2.approx.f32 %0,%1;" : "=f"(t2) : "f"(d[2]));
            asm("ex2.approx.f32 %0,%1;" : "=f"(t3) : "f"(d[3]));
            e[s][0] = t0; e[s][1] = t1;
            e[s][2] = t2; e[s][3] = t3;
            ls0 += t0 + t1;
            ls1 += t2 + t3;
            // unnormalized A store; rescaled by this same lane at the end.
            // quads write 8 contiguous floats = full 32B sectors (R10 pattern)
            *(float2*)(Ar1 + t*8) = make_float2(t0, t1);
            *(float2*)(Ar2 + t*8) = make_float2(t2, t3);
        }
        // repack unnormalized e -> A-fragment (m16 x k16), split hi/lo
        uint32_t ahi[4], alo[4];
        split2(e[0][0], e[0][1], ahi[0], alo[0]);
        split2(e[0][2], e[0][3], ahi[1], alo[1]);
        split2(e[1][0], e[1][1], ahi[2], alo[2]);
        split2(e[1][2], e[1][3], ahi[3], alo[3]);
        // AV: two d-tiles (cols 0..7, 8..15); kc-parity accumulator sets
        float* accL = (kc & 1) ? cC : cA;
        float* accR = (kc & 1) ? cD : cB;
        {
            uint32_t vb[2], vl2[2];
            *(uint2*)vb  = *(const uint2*)(vhi + ((kc*2 + 0)*32 + lane)*2);
            *(uint2*)vl2 = *(const uint2*)(vlo + ((kc*2 + 0)*32 + lane)*2);
            mma_bf16(accL, ahi, vb);
            mma_bf16(accL, ahi, vl2);
            mma_bf16(accL, alo, vb);
        }
        {
            uint32_t vb[2], vl2[2];
            *(uint2*)vb  = *(const uint2*)(vhi + ((kc*2 + 1)*32 + lane)*2);
            *(uint2*)vl2 = *(const uint2*)(vlo + ((kc*2 + 1)*32 + lane)*2);
            mma_bf16(accR, ahi, vb);
            mma_bf16(accR, ahi, vl2);
            mma_bf16(accR, alo, vb);
        }
    }

    // ---- row sums -> inverses (quad reduce over tg) ----
    ls0 += __shfl_xor_sync(0xffffffffu, ls0, 1);
    ls0 += __shfl_xor_sync(0xffffffffu, ls0, 2);
    ls1 += __shfl_xor_sync(0xffffffffu, ls1, 1);
    ls1 += __shfl_xor_sync(0xffffffffu, ls1, 2);
    float inv0 = 1.0f / ls0, inv1 = 1.0f / ls1;

    // ---- epilogue: Hcat = (cA+cC, cB+cD) * inv ----
    {
        int b = bh / NH, h = bh - (bh / NH)*NH;
        float* Hp = g_Hcat + ((size_t)(b*S_ + q0 + warp*16))*DM + h*DK;
        *(float2*)(Hp + gid*DM + tg*2) =
            make_float2((cA[0]+cC[0])*inv0, (cA[1]+cC[1])*inv0);
        *(float2*)(Hp + (gid+8)*DM + tg*2) =
            make_float2((cA[2]+cC[2])*inv1, (cA[3]+cC[3])*inv1);
        *(float2*)(Hp + gid*DM + 8 + tg*2) =
            make_float2((cB[0]+cD[0])*inv0, (cB[1]+cD[1])*inv0);
        *(float2*)(Hp + (gid+8)*DM + 8 + tg*2) =
            make_float2((cB[2]+cD[2])*inv1, (cB[3]+cD[3])*inv1);
    }

    // ---- rescale: each lane re-reads/writes exactly what it stored ----
#pragma unroll 4
    for (int t = 0; t < 128; t++) {
        float2 a0 = *(float2*)(Ar1 + t*8);
        float2 a1 = *(float2*)(Ar2 + t*8);
        a0.x *= inv0; a0.y *= inv0;
        a1.x *= inv1; a1.y *= inv1;
        *(float2*)(Ar1 + t*8) = a0;
        *(float2*)(Ar2 + t*8) = a1;
    }
}

// ---------------------------------------------------------------------------
extern "C" void kernel_launch(void* const* d_in, const int* in_sizes, int n_in,
                              void* d_out, int out_size)
{
    const float* Xq = (const float*)d_in[0];
    const float* Xk = (const float*)d_in[1];
    const float* Xv = (const float*)d_in[2];
    const float* Wq = (const float*)d_in[3];
    const float* bq = (const float*)d_in[4];
    const float* Wk = (const float*)d_in[5];
    const float* bk = (const float*)d_in[6];
    const float* Wv = (const float*)d_in[7];
    const float* bv = (const float*)d_in[8];
    const float* Wh = (const float*)d_in[9];
    const float* bh = (const float*)d_in[10];

    float* outH = (float*)d_out;
    float* outA = (float*)d_out + H_ELEMS;

    cudaFuncSetAttribute(attn_mma, cudaFuncAttributeMaxDynamicSharedMemorySize, SMEM_BYTES);

    qkv48<<<dim3(256, 3), 384>>>(Xq, Wq, bq, Xk, Wk, bk, Xv, Wv, bv);
    attn_mma<<<dim3(4, BH_), 512, SMEM_BYTES>>>(outA);
    proj48<<<256, 384>>>(Wh, bh, outH);
}

// round 15
// speedup vs baseline: 1.6558x; 1.6514x over previous
#include <cuda_runtime.h>
#include <cuda_bf16.h>
#include <math.h>
#include <stdint.h>

#define B_   32
#define S_   1024
#define DM   48
#define NH   3
#define DK   16
#define BH_  (B_*NH)            // 96
#define H_ELEMS (B_*S_*DM)      // 1572864

typedef unsigned long long ull;

// Scratch (no allocations allowed)
__device__ float g_Q[BH_*S_*DK];
__device__ float g_K[BH_*S_*DK];
__device__ float g_V[BH_*S_*DK];
__device__ float g_Hcat[B_*S_*DM];

// ---------------------------------------------------------------------------
// Linear kernels. Xs rows padded to 50 floats: scalar LDS bank pattern
// r0*50 mod 32 (gcd(18,32)=2) => max 2-way conflict vs 16-way at stride 48.
// ---------------------------------------------------------------------------
__device__ __forceinline__ void lin_core(const float* __restrict__ X,
    const float* __restrict__ W, const float* __restrict__ bias,
    int row0, float scale, float* __restrict__ out, int headsplit)
{
    __shared__ float Ws[48*49];
    __shared__ float bs[48];
    __shared__ __align__(8) float Xs[128*50];
    int tid = threadIdx.x;
    for (int i = tid; i < 48*48; i += 384) Ws[(i/48)*49 + (i%48)] = W[i];
    if (tid < 48) bs[tid] = bias[tid];
    // X rows -> padded smem via float2 (row stride 200B, 8B-aligned)
    const float2* Xg2 = (const float2*)(X + row0*48);
    for (int i = tid; i < 128*24; i += 384) {
        int r = i / 24, c2 = i % 24;
        *(float2*)&Xs[r*50 + c2*2] = Xg2[i];
    }
    __syncthreads();

    int r0 = tid / 12, jg = tid % 12;
    float acc[4][4];
#pragma unroll
    for (int rr = 0; rr < 4; rr++)
#pragma unroll
        for (int jj = 0; jj < 4; jj++) acc[rr][jj] = bs[jg*4 + jj];

#pragma unroll 4
    for (int c = 0; c < 48; c++) {
        float xv[4], wv[4];
#pragma unroll
        for (int rr = 0; rr < 4; rr++) xv[rr] = Xs[(r0 + 32*rr)*50 + c];
#pragma unroll
        for (int jj = 0; jj < 4; jj++) wv[jj] = Ws[(jg*4 + jj)*49 + c];
#pragma unroll
        for (int rr = 0; rr < 4; rr++)
#pragma unroll
            for (int jj = 0; jj < 4; jj++)
                acc[rr][jj] = fmaf(xv[rr], wv[jj], acc[rr][jj]);
    }

    int j0 = jg * 4;
#pragma unroll
    for (int rr = 0; rr < 4; rr++) {
        int grow = row0 + r0 + 32*rr;
        float4 v = make_float4(acc[rr][0]*scale, acc[rr][1]*scale,
                               acc[rr][2]*scale, acc[rr][3]*scale);
        if (headsplit) {
            int b = grow >> 10, s = grow & 1023;
            int h = j0 >> 4,  d = j0 & 15;
            *(float4*)(out + ((b*NH + h)*S_ + s)*DK + d) = v;
        } else {
            *(float4*)(out + grow*48 + j0) = v;
        }
    }
}

__global__ __launch_bounds__(384) void qkv48(
    const float* __restrict__ Xq, const float* __restrict__ Wq, const float* __restrict__ bq,
    const float* __restrict__ Xk, const float* __restrict__ Wk, const float* __restrict__ bk,
    const float* __restrict__ Xv, const float* __restrict__ Wv, const float* __restrict__ bv)
{
    int m = blockIdx.y;
    const float *X, *W, *bb; float* dst; float scale;
    // Q scale folds 1/sqrt(dk) AND log2(e): attention uses ex2 directly.
    if (m == 0)      { X = Xq; W = Wq; bb = bq; dst = g_Q; scale = 0.25f * 1.4426950408889634f; }
    else if (m == 1) { X = Xk; W = Wk; bb = bk; dst = g_K; scale = 1.0f; }
    else             { X = Xv; W = Wv; bb = bv; dst = g_V; scale = 1.0f; }
    lin_core(X, W, bb, blockIdx.x * 128, scale, dst, 1);
}

__global__ __launch_bounds__(384) void proj48(
    const float* __restrict__ Wh, const float* __restrict__ bhp, float* __restrict__ out)
{
    lin_core((const float*)g_Hcat, Wh, bhp, blockIdx.x * 128, 1.0f, out, 0);
}

// ---------------------------------------------------------------------------
// split fp32 pair -> (bf16x2 hi, bf16x2 lo). Low 16 bits = first value.
// ---------------------------------------------------------------------------
__device__ __forceinline__ void split2(float e0, float e1, uint32_t& h2, uint32_t& l2) {
    uint32_t h;
    asm("cvt.rn.bf16x2.f32 %0, %1, %2;" : "=r"(h) : "f"(e1), "f"(e0));
    float h0 = __uint_as_float(h << 16);
    float h1 = __uint_as_float(h & 0xFFFF0000u);
    uint32_t l;
    asm("cvt.rn.bf16x2.f32 %0, %1, %2;" : "=r"(l) : "f"(e1 - h1), "f"(e0 - h0));
    h2 = h; l2 = l;
}

// mma.sync m16n8k16 row.col f32.bf16.bf16.f32, D accumulates in place.
__device__ __forceinline__ void mma_bf16(float d[4], const uint32_t a[4], const uint32_t b[2]) {
    asm volatile(
        "mma.sync.aligned.m16n8k16.row.col.f32.bf16.bf16.f32 "
        "{%0,%1,%2,%3}, {%4,%5,%6,%7}, {%8,%9}, {%0,%1,%2,%3};"
        : "+f"(d[0]), "+f"(d[1]), "+f"(d[2]), "+f"(d[3])
        : "r"(a[0]), "r"(a[1]), "r"(a[2]), "r"(a[3]), "r"(b[0]), "r"(b[1]));
}

// smem layout (u32 units): khi[8192] klo[8192] vhi[8192] vlo[8192]
#define SMO_KHI   0
#define SMO_KLO   8192
#define SMO_VHI   16384
#define SMO_VLO   24576
#define SMEM_BYTES (32768 * 4)   // 131072

// ---------------------------------------------------------------------------
// Tensor-core attention via mma.sync (R10 structure — proven 186us total).
// CTA = (qtile of 256 rows, bh). 512 thr = 16 warps; warp owns 16 q rows.
// K/V pre-split to bf16 hi/lo fragments in smem, built by DIRECT gmem
// gathers (coalesced-enough) — no smem staging round-trip.
// Pass 1: scores = 3x split MMA -> ex2 -> row sums (quad reduce) -> inv.
// Pass 2: recompute scores, normalize, quad-sector-coalesced STG.64 A
//         stores, lane-local repack -> AV = 3x split MMA per d-tile.
// Epilogue: Hcat direct (pre-normalized).
// ---------------------------------------------------------------------------
__global__ __launch_bounds__(512, 1) void attn_mma(float* __restrict__ Aout)
{
    extern __shared__ __align__(16) uint32_t smu[];
    uint32_t* khi = smu + SMO_KHI;
    uint32_t* klo = smu + SMO_KLO;
    uint32_t* vhi = smu + SMO_VHI;
    uint32_t* vlo = smu + SMO_VLO;

    int qt = blockIdx.x, bh = blockIdx.y;
    int tid = threadIdx.x, warp = tid >> 5, lane = tid & 31;
    int tg = lane & 3, gid = lane >> 2;
    int q0 = qt * 256;

    // ---- build K fragments directly from gmem ----
    const float* Kg = g_K + bh*(S_*DK);
    for (int e = tid; e < 8192; e += 512) {
        int t = e >> 6, rem = e & 63, reg = rem >> 5, ln = rem & 31;
        int krow = t*8 + (ln >> 2), dk = reg*8 + (ln & 3)*2;
        float2 v = *(const float2*)(Kg + krow*16 + dk);
        uint32_t h, l; split2(v.x, v.y, h, l);
        khi[(t*32 + ln)*2 + reg] = h;
        klo[(t*32 + ln)*2 + reg] = l;
    }
    // ---- build V fragments directly from gmem ----
    const float* Vg = g_V + bh*(S_*DK);
    for (int e = tid; e < 8192; e += 512) {
        int kc = e >> 7, rem = e & 127, t = rem >> 6, reg = (rem >> 5) & 1, ln = rem & 31;
        int k = kc*16 + reg*8 + (ln & 3)*2, d = t*8 + (ln >> 2);
        float v0 = Vg[k*16 + d];
        float v1 = Vg[(k + 1)*16 + d];
        uint32_t h, l; split2(v0, v1, h, l);
        vhi[((kc*2 + t)*32 + ln)*2 + reg] = h;
        vlo[((kc*2 + t)*32 + ln)*2 + reg] = l;
    }

    // ---- Q A-fragment (m16 x k16 = one MMA step), split hi/lo ----
    uint32_t qhi[4], qlo[4];
    {
        const float* Qp = g_Q + (bh*S_ + q0 + warp*16)*DK;
        float2 x;
        x = *(const float2*)(Qp + gid*16 + tg*2);           split2(x.x, x.y, qhi[0], qlo[0]);
        x = *(const float2*)(Qp + (gid+8)*16 + tg*2);       split2(x.x, x.y, qhi[1], qlo[1]);
        x = *(const float2*)(Qp + gid*16 + tg*2 + 8);       split2(x.x, x.y, qhi[2], qlo[2]);
        x = *(const float2*)(Qp + (gid+8)*16 + tg*2 + 8);   split2(x.x, x.y, qhi[3], qlo[3]);
    }
    __syncthreads();

    // ---- pass 1: row sums ----
    float ls0 = 0.f, ls1 = 0.f;
#pragma unroll 2
    for (int t = 0; t < 128; t++) {
        uint32_t kb[2], kl2[2];
        *(uint2*)kb  = *(const uint2*)(khi + (t*32 + lane)*2);
        *(uint2*)kl2 = *(const uint2*)(klo + (t*32 + lane)*2);
        float d[4] = {0.f, 0.f, 0.f, 0.f};
        mma_bf16(d, qhi, kb);
        mma_bf16(d, qhi, kl2);
        mma_bf16(d, qlo, kb);
        float e0, e1, e2, e3;
        asm("ex2.approx.f32 %0,%1;" : "=f"(e0) : "f"(d[0]));
        asm("ex2.approx.f32 %0,%1;" : "=f"(e1) : "f"(d[1]));
        asm("ex2.approx.f32 %0,%1;" : "=f"(e2) : "f"(d[2]));
        asm("ex2.approx.f32 %0,%1;" : "=f"(e3) : "f"(d[3]));
        ls0 += e0 + e1;
        ls1 += e2 + e3;
    }
    ls0 += __shfl_xor_sync(0xffffffffu, ls0, 1);
    ls0 += __shfl_xor_sync(0xffffffffu, ls0, 2);
    ls1 += __shfl_xor_sync(0xffffffffu, ls1, 1);
    ls1 += __shfl_xor_sync(0xffffffffu, ls1, 2);
    float inv0 = 1.0f / ls0, inv1 = 1.0f / ls1;

    // ---- pass 2: normalized A stores + AV ----
    float cA[4] = {0.f, 0.f, 0.f, 0.f};   // d cols 0..7
    float cB[4] = {0.f, 0.f, 0.f, 0.f};   // d cols 8..15
    float* Ab = Aout + ((size_t)(bh*S_ + q0 + warp*16))*S_;
    float* Ar1 = Ab + (size_t)gid*S_ + tg*2;
    float* Ar2 = Ab + (size_t)(gid+8)*S_ + tg*2;

#pragma unroll 1
    for (int kc = 0; kc < 64; kc++) {
        float e[2][4];
#pragma unroll
        for (int s = 0; s < 2; s++) {
            int t = kc*2 + s;
            uint32_t kb[2], kl2[2];
            *(uint2*)kb  = *(const uint2*)(khi + (t*32 + lane)*2);
            *(uint2*)kl2 = *(const uint2*)(klo + (t*32 + lane)*2);
            float d[4] = {0.f, 0.f, 0.f, 0.f};
            mma_bf16(d, qhi, kb);
            mma_bf16(d, qhi, kl2);
            mma_bf16(d, qlo, kb);
            float t0, t1, t2, t3;
            asm("ex2.approx.f32 %0,%1;" : "=f"(t0) : "f"(d[0]));
            asm("ex2.approx.f32 %0,%1;" : "=f"(t1) : "f"(d[1]));
            asm("ex2.approx.f32 %0,%1;" : "=f"(t2) : "f"(d[2]));
            asm("ex2.approx.f32 %0,%1;" : "=f"(t3) : "f"(d[3]));
            e[s][0] = t0 * inv0; e[s][1] = t1 * inv0;
            e[s][2] = t2 * inv1; e[s][3] = t3 * inv1;
            // quads write 8 contiguous floats = full 32B sectors (R10 pattern)
            *(float2*)(Ar1 + t*8) = make_float2(e[s][0], e[s][1]);
            *(float2*)(Ar2 + t*8) = make_float2(e[s][2], e[s][3]);
        }
        // repack normalized e -> A-fragment (m16 x k16), split hi/lo
        uint32_t ahi[4], alo[4];
        split2(e[0][0], e[0][1], ahi[0], alo[0]);
        split2(e[0][2], e[0][3], ahi[1], alo[1]);
        split2(e[1][0], e[1][1], ahi[2], alo[2]);
        split2(e[1][2], e[1][3], ahi[3], alo[3]);
        // AV: two d-tiles (cols 0..7, 8..15)
        {
            uint32_t vb[2], vl2[2];
            *(uint2*)vb  = *(const uint2*)(vhi + ((kc*2 + 0)*32 + lane)*2);
            *(uint2*)vl2 = *(const uint2*)(vlo + ((kc*2 + 0)*32 + lane)*2);
            mma_bf16(cA, ahi, vb);
            mma_bf16(cA, ahi, vl2);
            mma_bf16(cA, alo, vb);
        }
        {
            uint32_t vb[2], vl2[2];
            *(uint2*)vb  = *(const uint2*)(vhi + ((kc*2 + 1)*32 + lane)*2);
            *(uint2*)vl2 = *(const uint2*)(vlo + ((kc*2 + 1)*32 + lane)*2);
            mma_bf16(cB, ahi, vb);
            mma_bf16(cB, ahi, vl2);
            mma_bf16(cB, alo, vb);
        }
    }

    // ---- epilogue: Hcat (already normalized) ----
    {
        int b = bh / NH, h = bh - (bh / NH)*NH;
        float* Hp = g_Hcat + ((size_t)(b*S_ + q0 + warp*16))*DM + h*DK;
        *(float2*)(Hp + gid*DM + tg*2)           = make_float2(cA[0], cA[1]);
        *(float2*)(Hp + (gid+8)*DM + tg*2)       = make_float2(cA[2], cA[3]);
        *(float2*)(Hp + gid*DM + 8 + tg*2)       = make_float2(cB[0], cB[1]);
        *(float2*)(Hp + (gid+8)*DM + 8 + tg*2)   = make_float2(cB[2], cB[3]);
    }
}

// ---------------------------------------------------------------------------
extern "C" void kernel_launch(void* const* d_in, const int* in_sizes, int n_in,
                              void* d_out, int out_size)
{
    const float* Xq = (const float*)d_in[0];
    const float* Xk = (const float*)d_in[1];
    const float* Xv = (const float*)d_in[2];
    const float* Wq = (const float*)d_in[3];
    const float* bq = (const float*)d_in[4];
    const float* Wk = (const float*)d_in[5];
    const float* bk = (const float*)d_in[6];
    const float* Wv = (const float*)d_in[7];
    const float* bv = (const float*)d_in[8];
    const float* Wh = (const float*)d_in[9];
    const float* bh = (const float*)d_in[10];

    float* outH = (float*)d_out;
    float* outA = (float*)d_out + H_ELEMS;

    cudaFuncSetAttribute(attn_mma, cudaFuncAttributeMaxDynamicSharedMemorySize, SMEM_BYTES);

    qkv48<<<dim3(256, 3), 384>>>(Xq, Wq, bq, Xk, Wk, bk, Xv, Wv, bv);
    attn_mma<<<dim3(4, BH_), 512, SMEM_BYTES>>>(outA);
    proj48<<<256, 384>>>(Wh, bh, outH);
}

// round 17
// speedup vs baseline: 1.7146x; 1.0355x over previous
#include <cuda_runtime.h>
#include <cuda_bf16.h>
#include <math.h>
#include <stdint.h>

#define B_   32
#define S_   1024
#define DM   48
#define NH   3
#define DK   16
#define BH_  (B_*NH)            // 96
#define H_ELEMS (B_*S_*DM)      // 1572864

typedef unsigned long long ull;

// Scratch (no allocations allowed)
__device__ float g_Q[BH_*S_*DK];
__device__ float g_K[BH_*S_*DK];
__device__ float g_V[BH_*S_*DK];
__device__ float g_Hcat[B_*S_*DM];

// ---------------------------------------------------------------------------
// Linear kernels (R15 padded variant — measured neutral vs R4, fewer regs)
// ---------------------------------------------------------------------------
__device__ __forceinline__ void lin_core(const float* __restrict__ X,
    const float* __restrict__ W, const float* __restrict__ bias,
    int row0, float scale, float* __restrict__ out, int headsplit)
{
    __shared__ float Ws[48*49];
    __shared__ float bs[48];
    __shared__ __align__(8) float Xs[128*50];
    int tid = threadIdx.x;
    for (int i = tid; i < 48*48; i += 384) Ws[(i/48)*49 + (i%48)] = W[i];
    if (tid < 48) bs[tid] = bias[tid];
    const float2* Xg2 = (const float2*)(X + row0*48);
    for (int i = tid; i < 128*24; i += 384) {
        int r = i / 24, c2 = i % 24;
        *(float2*)&Xs[r*50 + c2*2] = Xg2[i];
    }
    __syncthreads();

    int r0 = tid / 12, jg = tid % 12;
    float acc[4][4];
#pragma unroll
    for (int rr = 0; rr < 4; rr++)
#pragma unroll
        for (int jj = 0; jj < 4; jj++) acc[rr][jj] = bs[jg*4 + jj];

#pragma unroll 4
    for (int c = 0; c < 48; c++) {
        float xv[4], wv[4];
#pragma unroll
        for (int rr = 0; rr < 4; rr++) xv[rr] = Xs[(r0 + 32*rr)*50 + c];
#pragma unroll
        for (int jj = 0; jj < 4; jj++) wv[jj] = Ws[(jg*4 + jj)*49 + c];
#pragma unroll
        for (int rr = 0; rr < 4; rr++)
#pragma unroll
            for (int jj = 0; jj < 4; jj++)
                acc[rr][jj] = fmaf(xv[rr], wv[jj], acc[rr][jj]);
    }

    int j0 = jg * 4;
#pragma unroll
    for (int rr = 0; rr < 4; rr++) {
        int grow = row0 + r0 + 32*rr;
        float4 v = make_float4(acc[rr][0]*scale, acc[rr][1]*scale,
                               acc[rr][2]*scale, acc[rr][3]*scale);
        if (headsplit) {
            int b = grow >> 10, s = grow & 1023;
            int h = j0 >> 4,  d = j0 & 15;
            *(float4*)(out + ((b*NH + h)*S_ + s)*DK + d) = v;
        } else {
            *(float4*)(out + grow*48 + j0) = v;
        }
    }
}

__global__ __launch_bounds__(384) void qkv48(
    const float* __restrict__ Xq, const float* __restrict__ Wq, const float* __restrict__ bq,
    const float* __restrict__ Xk, const float* __restrict__ Wk, const float* __restrict__ bk,
    const float* __restrict__ Xv, const float* __restrict__ Wv, const float* __restrict__ bv)
{
    int m = blockIdx.y;
    const float *X, *W, *bb; float* dst; float scale;
    // Q scale folds 1/sqrt(dk) AND log2(e): attention uses ex2 directly.
    if (m == 0)      { X = Xq; W = Wq; bb = bq; dst = g_Q; scale = 0.25f * 1.4426950408889634f; }
    else if (m == 1) { X = Xk; W = Wk; bb = bk; dst = g_K; scale = 1.0f; }
    else             { X = Xv; W = Wv; bb = bv; dst = g_V; scale = 1.0f; }
    lin_core(X, W, bb, blockIdx.x * 128, scale, dst, 1);
}

__global__ __launch_bounds__(384) void proj48(
    const float* __restrict__ Wh, const float* __restrict__ bhp, float* __restrict__ out)
{
    lin_core((const float*)g_Hcat, Wh, bhp, blockIdx.x * 128, 1.0f, out, 0);
}

// ---------------------------------------------------------------------------
// split fp32 pair -> (bf16x2 hi, bf16x2 lo). Low 16 bits = first value.
// ---------------------------------------------------------------------------
__device__ __forceinline__ void split2(float e0, float e1, uint32_t& h2, uint32_t& l2) {
    uint32_t h;
    asm("cvt.rn.bf16x2.f32 %0, %1, %2;" : "=r"(h) : "f"(e1), "f"(e0));
    float h0 = __uint_as_float(h << 16);
    float h1 = __uint_as_float(h & 0xFFFF0000u);
    uint32_t l;
    asm("cvt.rn.bf16x2.f32 %0, %1, %2;" : "=r"(l) : "f"(e1 - h1), "f"(e0 - h0));
    h2 = h; l2 = l;
}

// mma.sync m16n8k16 row.col f32.bf16.bf16.f32, D accumulates in place.
__device__ __forceinline__ void mma_bf16(float d[4], const uint32_t a[4], const uint32_t b[2]) {
    asm volatile(
        "mma.sync.aligned.m16n8k16.row.col.f32.bf16.bf16.f32 "
        "{%0,%1,%2,%3}, {%4,%5,%6,%7}, {%8,%9}, {%0,%1,%2,%3};"
        : "+f"(d[0]), "+f"(d[1]), "+f"(d[2]), "+f"(d[3])
        : "r"(a[0]), "r"(a[1]), "r"(a[2]), "r"(a[3]), "r"(b[0]), "r"(b[1]));
}

// smem layout (u32 units): khi[8192] klo[8192] vhi[8192] vlo[8192] stage[4096]
#define SMO_KHI   0
#define SMO_KLO   8192
#define SMO_VHI   16384
#define SMO_VLO   24576
#define SMO_STAGE 32768
#define SMEM_BYTES ((32768 + 4096) * 4)   // 147456

// ---------------------------------------------------------------------------
// Tensor-core attention via mma.sync — R10 structure exactly, ONE change:
// AV accumulators split by kc parity (halves the serial HMMA RAW chain;
// fp32 add-order change only, numerically safe).
// Pass 1 keeps the FULL 3-MMA split: normalizer errors are row-correlated
// (no sqrt-N averaging) — the 1-MMA variant measured rel_err 1.1e-3.
// CTA = (qtile of 256 rows, bh). 512 thr = 16 warps; warp owns 16 q rows.
// ---------------------------------------------------------------------------
__global__ __launch_bounds__(512, 1) void attn_mma(float* __restrict__ Aout)
{
    extern __shared__ __align__(16) uint32_t smu[];
    uint32_t* khi = smu + SMO_KHI;
    uint32_t* klo = smu + SMO_KLO;
    uint32_t* vhi = smu + SMO_VHI;
    uint32_t* vlo = smu + SMO_VLO;
    float* stage  = (float*)(smu + SMO_STAGE);

    int qt = blockIdx.x, bh = blockIdx.y;
    int tid = threadIdx.x, warp = tid >> 5, lane = tid & 31;
    int tg = lane & 3, gid = lane >> 2;
    int q0 = qt * 256;

    // ---- build K fragments (4 rounds of 256 seq rows, staged — R10) ----
    const float4* Kg4 = (const float4*)(g_K + bh*(S_*DK));
    for (int r = 0; r < 4; r++) {
        for (int i = tid; i < 1024; i += 512)
            ((float4*)stage)[i] = Kg4[r*1024 + i];
        __syncthreads();
        for (int e = tid; e < 2048; e += 512) {
            int tl = e >> 6, rem = e & 63, reg = rem >> 5, ln = rem & 31;
            int krow = tl*8 + (ln >> 2), dk = reg*8 + (ln & 3)*2;
            float2 v = *(const float2*)(stage + krow*16 + dk);
            uint32_t h, l; split2(v.x, v.y, h, l);
            int t = r*32 + tl;
            khi[(t*32 + ln)*2 + reg] = h;
            klo[(t*32 + ln)*2 + reg] = l;
        }
        __syncthreads();
    }
    // ---- build V fragments (4 rounds, staged — R10) ----
    const float4* Vg4 = (const float4*)(g_V + bh*(S_*DK));
    for (int r = 0; r < 4; r++) {
        for (int i = tid; i < 1024; i += 512)
            ((float4*)stage)[i] = Vg4[r*1024 + i];
        __syncthreads();
        for (int e = tid; e < 2048; e += 512) {
            int kcl = e >> 7, rem = e & 127, t = rem >> 6, reg = (rem >> 5) & 1, ln = rem & 31;
            int klc = kcl*16 + reg*8 + (ln & 3)*2, d = t*8 + (ln >> 2);
            float v0 = stage[klc*16 + d];
            float v1 = stage[(klc + 1)*16 + d];
            uint32_t h, l; split2(v0, v1, h, l);
            int kc = r*16 + kcl;
            vhi[((kc*2 + t)*32 + ln)*2 + reg] = h;
            vlo[((kc*2 + t)*32 + ln)*2 + reg] = l;
        }
        __syncthreads();
    }

    // ---- Q A-fragment (m16 x k16 = one MMA step), split hi/lo ----
    uint32_t qhi[4], qlo[4];
    {
        const float* Qp = g_Q + (bh*S_ + q0 + warp*16)*DK;
        float2 x;
        x = *(const float2*)(Qp + gid*16 + tg*2);           split2(x.x, x.y, qhi[0], qlo[0]);
        x = *(const float2*)(Qp + (gid+8)*16 + tg*2);       split2(x.x, x.y, qhi[1], qlo[1]);
        x = *(const float2*)(Qp + gid*16 + tg*2 + 8);       split2(x.x, x.y, qhi[2], qlo[2]);
        x = *(const float2*)(Qp + (gid+8)*16 + tg*2 + 8);   split2(x.x, x.y, qhi[3], qlo[3]);
    }

    // ---- pass 1: row sums (full 3-MMA split — precision required) ----
    float ls0 = 0.f, ls1 = 0.f;
#pragma unroll 2
    for (int t = 0; t < 128; t++) {
        uint32_t kb[2], kl2[2];
        *(uint2*)kb  = *(const uint2*)(khi + (t*32 + lane)*2);
        *(uint2*)kl2 = *(const uint2*)(klo + (t*32 + lane)*2);
        float d[4] = {0.f, 0.f, 0.f, 0.f};
        mma_bf16(d, qhi, kb);
        mma_bf16(d, qhi, kl2);
        mma_bf16(d, qlo, kb);
        float e0, e1, e2, e3;
        asm("ex2.approx.f32 %0,%1;" : "=f"(e0) : "f"(d[0]));
        asm("ex2.approx.f32 %0,%1;" : "=f"(e1) : "f"(d[1]));
        asm("ex2.approx.f32 %0,%1;" : "=f"(e2) : "f"(d[2]));
        asm("ex2.approx.f32 %0,%1;" : "=f"(e3) : "f"(d[3]));
        ls0 += e0 + e1;
        ls1 += e2 + e3;
    }
    ls0 += __shfl_xor_sync(0xffffffffu, ls0, 1);
    ls0 += __shfl_xor_sync(0xffffffffu, ls0, 2);
    ls1 += __shfl_xor_sync(0xffffffffu, ls1, 1);
    ls1 += __shfl_xor_sync(0xffffffffu, ls1, 2);
    float inv0 = 1.0f / ls0, inv1 = 1.0f / ls1;

    // ---- pass 2: normalized A stores + AV (kc-parity accumulators) ----
    float cA[4] = {0.f, 0.f, 0.f, 0.f};   // d cols 0..7,  even kc
    float cB[4] = {0.f, 0.f, 0.f, 0.f};   // d cols 8..15, even kc
    float cC[4] = {0.f, 0.f, 0.f, 0.f};   // d cols 0..7,  odd kc
    float cD[4] = {0.f, 0.f, 0.f, 0.f};   // d cols 8..15, odd kc
    float* Ab = Aout + ((size_t)(bh*S_ + q0 + warp*16))*S_;
    float* Ar1 = Ab + (size_t)gid*S_ + tg*2;
    float* Ar2 = Ab + (size_t)(gid+8)*S_ + tg*2;

#pragma unroll 1
    for (int kc = 0; kc < 64; kc++) {
        float e[2][4];
#pragma unroll
        for (int s = 0; s < 2; s++) {
            int t = kc*2 + s;
            uint32_t kb[2], kl2[2];
            *(uint2*)kb  = *(const uint2*)(khi + (t*32 + lane)*2);
            *(uint2*)kl2 = *(const uint2*)(klo + (t*32 + lane)*2);
            float d[4] = {0.f, 0.f, 0.f, 0.f};
            mma_bf16(d, qhi, kb);
            mma_bf16(d, qhi, kl2);
            mma_bf16(d, qlo, kb);
            float t0, t1, t2, t3;
            asm("ex2.approx.f32 %0,%1;" : "=f"(t0) : "f"(d[0]));
            asm("ex2.approx.f32 %0,%1;" : "=f"(t1) : "f"(d[1]));
            asm("ex2.approx.f32 %0,%1;" : "=f"(t2) : "f"(d[2]));
            asm("ex2.approx.f32 %0,%1;" : "=f"(t3) : "f"(d[3]));
            e[s][0] = t0 * inv0; e[s][1] = t1 * inv0;
            e[s][2] = t2 * inv1; e[s][3] = t3 * inv1;
            // quads write 8 contiguous floats = full 32B sectors (R10 pattern)
            *(float2*)(Ar1 + t*8) = make_float2(e[s][0], e[s][1]);
            *(float2*)(Ar2 + t*8) = make_float2(e[s][2], e[s][3]);
        }
        // repack normalized e -> A-fragment (m16 x k16), split hi/lo
        uint32_t ahi[4], alo[4];
        split2(e[0][0], e[0][1], ahi[0], alo[0]);
        split2(e[0][2], e[0][3], ahi[1], alo[1]);
        split2(e[1][0], e[1][1], ahi[2], alo[2]);
        split2(e[1][2], e[1][3], ahi[3], alo[3]);
        // AV: two d-tiles (cols 0..7, 8..15); kc-parity accumulator sets
        float* accL = (kc & 1) ? cC : cA;
        float* accR = (kc & 1) ? cD : cB;
        {
            uint32_t vb[2], vl2[2];
            *(uint2*)vb  = *(const uint2*)(vhi + ((kc*2 + 0)*32 + lane)*2);
            *(uint2*)vl2 = *(const uint2*)(vlo + ((kc*2 + 0)*32 + lane)*2);
            mma_bf16(accL, ahi, vb);
            mma_bf16(accL, ahi, vl2);
            mma_bf16(accL, alo, vb);
        }
        {
            uint32_t vb[2], vl2[2];
            *(uint2*)vb  = *(const uint2*)(vhi + ((kc*2 + 1)*32 + lane)*2);
            *(uint2*)vl2 = *(const uint2*)(vlo + ((kc*2 + 1)*32 + lane)*2);
            mma_bf16(accR, ahi, vb);
            mma_bf16(accR, ahi, vl2);
            mma_bf16(accR, alo, vb);
        }
    }

    // ---- epilogue: Hcat = (even + odd accumulators), already normalized ----
    {
        int b = bh / NH, h = bh - (bh / NH)*NH;
        float* Hp = g_Hcat + ((size_t)(b*S_ + q0 + warp*16))*DM + h*DK;
        *(float2*)(Hp + gid*DM + tg*2)         = make_float2(cA[0]+cC[0], cA[1]+cC[1]);
        *(float2*)(Hp + (gid+8)*DM + tg*2)     = make_float2(cA[2]+cC[2], cA[3]+cC[3]);
        *(float2*)(Hp + gid*DM + 8 + tg*2)     = make_float2(cB[0]+cD[0], cB[1]+cD[1]);
        *(float2*)(Hp + (gid+8)*DM + 8 + tg*2) = make_float2(cB[2]+cD[2], cB[3]+cD[3]);
    }
}

// ---------------------------------------------------------------------------
extern "C" void kernel_launch(void* const* d_in, const int* in_sizes, int n_in,
                              void* d_out, int out_size)
{
    const float* Xq = (const float*)d_in[0];
    const float* Xk = (const float*)d_in[1];
    const float* Xv = (const float*)d_in[2];
    const float* Wq = (const float*)d_in[3];
    const float* bq = (const float*)d_in[4];
    const float* Wk = (const float*)d_in[5];
    const float* bk = (const float*)d_in[6];
    const float* Wv = (const float*)d_in[7];
    const float* bv = (const float*)d_in[8];
    const float* Wh = (const float*)d_in[9];
    const float* bh = (const float*)d_in[10];

    float* outH = (float*)d_out;
    float* outA = (float*)d_out + H_ELEMS;

    cudaFuncSetAttribute(attn_mma, cudaFuncAttributeMaxDynamicSharedMemorySize, SMEM_BYTES);

    qkv48<<<dim3(256, 3), 384>>>(Xq, Wq, bq, Xk, Wk, bk, Xv, Wv, bv);
    attn_mma<<<dim3(4, BH_), 512, SMEM_BYTES>>>(outA);
    proj48<<<256, 384>>>(Wh, bh, outH);
}